// round 7
// baseline (speedup 1.0000x reference)
#include <cuda_runtime.h>
#include <cuda_bf16.h>
#include <math.h>
#include <stdint.h>

#define B_   4
#define S_   2048
#define EMB_ 1024
#define H_   16
#define HD_  64
#define M_   (B_ * S_)   // 8192

// ---- ptx helpers (mma.sync / ldmatrix / cp.async) — baseline sm_103 legal --
__device__ __forceinline__ uint32_t smem_u32(const void* p) {
    uint32_t a;
    asm("{ .reg .u64 t; cvta.to.shared.u64 t, %1; cvt.u32.u64 %0, t; }"
        : "=r"(a) : "l"(p));
    return a;
}
__device__ __forceinline__ void cpa16(uint32_t dst, const void* src) {
    asm volatile("cp.async.cg.shared.global [%0], [%1], 16;" :: "r"(dst), "l"(src) : "memory");
}
#define CPA_COMMIT() asm volatile("cp.async.commit_group;" ::: "memory")
#define CPA_WAIT1()  asm volatile("cp.async.wait_group 1;"  ::: "memory")

#define LDSM4(r0, r1, r2, r3, addr) \
    asm volatile("ldmatrix.sync.aligned.m8n8.x4.shared.b16 {%0,%1,%2,%3}, [%4];" \
        : "=r"(r0), "=r"(r1), "=r"(r2), "=r"(r3) : "r"(addr))
#define LDSM4T(r0, r1, r2, r3, addr) \
    asm volatile("ldmatrix.sync.aligned.m8n8.x4.trans.shared.b16 {%0,%1,%2,%3}, [%4];" \
        : "=r"(r0), "=r"(r1), "=r"(r2), "=r"(r3) : "r"(addr))

#define MMA16816(c, a, b0, b1) \
    asm volatile("mma.sync.aligned.m16n8k16.row.col.f32.bf16.bf16.f32 " \
        "{%0,%1,%2,%3},{%4,%5,%6,%7},{%8,%9},{%0,%1,%2,%3};" \
        : "+f"((c)[0]), "+f"((c)[1]), "+f"((c)[2]), "+f"((c)[3]) \
        : "r"((a)[0]), "r"((a)[1]), "r"((a)[2]), "r"((a)[3]), "r"(b0), "r"(b1))

__device__ __forceinline__ uint32_t packbf(float lo, float hi) {
    uint32_t r;
    asm("cvt.rn.bf16x2.f32 %0, %1, %2;" : "=r"(r) : "f"(hi), "f"(lo));
    return r;
}
__device__ __forceinline__ float bflo(uint32_t p) { return __uint_as_float(p << 16); }
__device__ __forceinline__ float bfhi(uint32_t p) { return __uint_as_float(p & 0xffff0000u); }
__device__ __forceinline__ float ex2(float x) {
    float r; asm("ex2.approx.f32 %0, %1;" : "=f"(r) : "f"(x)); return r;
}

// ---------------- scratch (device globals; no allocation allowed) ----------
__device__ __align__(16) __nv_bfloat16 g_xhi[(size_t)M_ * EMB_];
__device__ __align__(16) __nv_bfloat16 g_xlo[(size_t)M_ * EMB_];
__device__ __align__(16) __nv_bfloat16 g_whi[(size_t)4 * EMB_ * EMB_];
__device__ __align__(16) __nv_bfloat16 g_wlo[(size_t)4 * EMB_ * EMB_];
__device__ __align__(16) __nv_bfloat16 g_qhi[(size_t)M_ * EMB_];
__device__ __align__(16) __nv_bfloat16 g_qlo[(size_t)M_ * EMB_];
__device__ __align__(16) __nv_bfloat16 g_khi[(size_t)M_ * EMB_];
__device__ __align__(16) __nv_bfloat16 g_klo[(size_t)M_ * EMB_];
__device__ __align__(16) __nv_bfloat16 g_vhi[(size_t)M_ * EMB_];
__device__ __align__(16) __nv_bfloat16 g_vlo[(size_t)M_ * EMB_];
__device__ __align__(16) __nv_bfloat16 g_ahi[(size_t)M_ * EMB_];
__device__ __align__(16) __nv_bfloat16 g_alo[(size_t)M_ * EMB_];

// ---------------- fp32 -> bf16 hi/lo split ----------------------------------
__global__ __launch_bounds__(256) void conv_split_x(
    const float* __restrict__ src, int n4)
{
    int i = blockIdx.x * 256 + threadIdx.x;
    if (i >= n4) return;
    float4 v = ((const float4*)src)[i];
    uint32_t h01 = packbf(v.x, v.y), h23 = packbf(v.z, v.w);
    uint32_t l01 = packbf(v.x - bflo(h01), v.y - bfhi(h01));
    uint32_t l23 = packbf(v.z - bflo(h23), v.w - bfhi(h23));
    ((uint32_t*)g_xhi)[2 * i] = h01; ((uint32_t*)g_xhi)[2 * i + 1] = h23;
    ((uint32_t*)g_xlo)[2 * i] = l01; ((uint32_t*)g_xlo)[2 * i + 1] = l23;
}
__global__ __launch_bounds__(256) void conv_split_w(
    const float* __restrict__ w0, const float* __restrict__ w1,
    const float* __restrict__ w2, const float* __restrict__ w3)
{
    const int which = blockIdx.y;
    const float* src = (which == 0) ? w0 : (which == 1) ? w1 : (which == 2) ? w2 : w3;
    __nv_bfloat16* hi = g_whi + (size_t)which * EMB_ * EMB_;
    __nv_bfloat16* lo = g_wlo + (size_t)which * EMB_ * EMB_;
    int i = blockIdx.x * 256 + threadIdx.x;
    float4 v = ((const float4*)src)[i];
    uint32_t h01 = packbf(v.x, v.y), h23 = packbf(v.z, v.w);
    uint32_t l01 = packbf(v.x - bflo(h01), v.y - bfhi(h01));
    uint32_t l23 = packbf(v.z - bflo(h23), v.w - bfhi(h23));
    ((uint32_t*)hi)[2 * i] = h01; ((uint32_t*)hi)[2 * i + 1] = h23;
    ((uint32_t*)lo)[2 * i] = l01; ((uint32_t*)lo)[2 * i + 1] = l23;
}

// ---------------- mma.sync GEMM: D = A @ W^T + bias -------------------------
// CTA tile 128x128, 256 threads, K chunk 32, 2-stage cp.async, 2 CTAs/SM.
constexpr int GSTRIDE = 80;                        // 32 bf16 = 64B data + 16 pad
constexpr int GMATSZ  = 128 * GSTRIDE;             // 10240 per matrix
constexpr int GSTAGE  = 4 * GMATSZ;                // 40960 (Ahi,Alo,Bhi,Blo)
constexpr int GEMM_SMEM = 2 * GSTAGE;              // 81920 -> 2 CTAs/SM

__device__ __forceinline__ void gload_chunk(
    uint32_t sbase, const __nv_bfloat16* Ahi, const __nv_bfloat16* Alo,
    const __nv_bfloat16* Bhi, const __nv_bfloat16* Blo,
    int row0, int col0, int k0, int tid)
{
    #pragma unroll
    for (int j = 0; j < 2048; j += 256) {
        int i   = j + tid;
        int mat = i >> 9;                 // 4 mats x 512 (128 rows x 4 cols)
        int r   = (i >> 2) & 127;
        int c   = i & 3;
        const __nv_bfloat16* m =
            (mat == 0) ? Ahi : (mat == 1) ? Alo : (mat == 2) ? Bhi : Blo;
        int gr = ((mat < 2) ? row0 : col0) + r;
        cpa16(sbase + mat * GMATSZ + r * GSTRIDE + c * 16,
              m + (size_t)gr * EMB_ + k0 + c * 8);
    }
    CPA_COMMIT();
}

// mode 0: A = x split, W = W[z]; write bf16 hi/lo Q/K/V in [B,H,S,hd]
// mode 1: A = attn split, W = W[3]; write fp32 outp[m*EMB+n]
__global__ __launch_bounds__(256, 2) void gemm_mma_kernel(
    const float* __restrict__ bq, const float* __restrict__ bk,
    const float* __restrict__ bv, float* __restrict__ outp, int mode)
{
    extern __shared__ char smem[];
    const uint32_t sb = smem_u32(smem);
    const int tid = threadIdx.x, wid = tid >> 5, lane = tid & 31;
    const int row0 = blockIdx.y * 128, col0 = blockIdx.x * 128;
    const int z = blockIdx.z;

    const __nv_bfloat16 *Ahi, *Alo, *Bhi, *Blo;
    const float* bias;
    if (mode == 0) {
        Ahi = g_xhi; Alo = g_xlo;
        Bhi = g_whi + (size_t)z * EMB_ * EMB_;
        Blo = g_wlo + (size_t)z * EMB_ * EMB_;
        bias = (z == 0) ? bq : (z == 1) ? bk : bv;
    } else {
        Ahi = g_ahi; Alo = g_alo;
        Bhi = g_whi + (size_t)3 * EMB_ * EMB_;
        Blo = g_wlo + (size_t)3 * EMB_ * EMB_;
        bias = bq;
    }

    const int wm = (wid & 1) * 64;
    const int wn = (wid >> 1) * 32;

    float c[4][4][4] = {};

    gload_chunk(sb,          Ahi, Alo, Bhi, Blo, row0, col0, 0,  tid);
    gload_chunk(sb + GSTAGE, Ahi, Alo, Bhi, Blo, row0, col0, 32, tid);

    const int a_row = wm + (lane & 7) + ((lane >> 3) & 1) * 8;
    const int a_kc  = ((lane >> 4) & 1) * 8;
    const int b_row = wn + (lane & 7) + ((lane >> 4) & 1) * 8;
    const int b_kc  = ((lane >> 3) & 1) * 8;

    for (int ch = 0; ch < 32; ++ch) {
        const int s = ch & 1;
        CPA_WAIT1();
        __syncthreads();
        const uint32_t st = sb + s * GSTAGE;

        #pragma unroll
        for (int kk = 0; kk < 32; kk += 16) {
            uint32_t bh[2][4], bl[2][4];
            #pragma unroll
            for (int pt = 0; pt < 2; ++pt) {
                uint32_t addr = st + 2 * GMATSZ + (b_row + pt * 16) * GSTRIDE
                              + (kk + b_kc) * 2;
                LDSM4(bh[pt][0], bh[pt][1], bh[pt][2], bh[pt][3], addr);
                LDSM4(bl[pt][0], bl[pt][1], bl[pt][2], bl[pt][3], addr + GMATSZ);
            }
            #pragma unroll
            for (int mt = 0; mt < 4; ++mt) {
                uint32_t addr = st + (a_row + mt * 16) * GSTRIDE
                              + (kk + a_kc) * 2;
                uint32_t ah[4], al[4];
                LDSM4(ah[0], ah[1], ah[2], ah[3], addr);
                LDSM4(al[0], al[1], al[2], al[3], addr + GMATSZ);
                #pragma unroll
                for (int nt = 0; nt < 4; ++nt) {
                    const int pt = nt >> 1, hf = (nt & 1) * 2;
                    MMA16816(c[mt][nt], ah, bh[pt][hf], bh[pt][hf + 1]);
                    MMA16816(c[mt][nt], ah, bl[pt][hf], bl[pt][hf + 1]);
                    MMA16816(c[mt][nt], al, bh[pt][hf], bh[pt][hf + 1]);
                }
            }
        }
        __syncthreads();
        if (ch + 2 < 32)
            gload_chunk(sb + s * GSTAGE, Ahi, Alo, Bhi, Blo,
                        row0, col0, (ch + 2) * 32, tid);
        else
            CPA_COMMIT();
    }

    #pragma unroll
    for (int mt = 0; mt < 4; ++mt) {
        #pragma unroll
        for (int nt = 0; nt < 4; ++nt) {
            int r = row0 + wm + mt * 16 + (lane >> 2);
            int n = col0 + wn + nt * 8 + (lane & 3) * 2;
            float2 bv2 = *(const float2*)&bias[n];
            float p0 = c[mt][nt][0] + bv2.x, p1 = c[mt][nt][1] + bv2.y;
            float p2 = c[mt][nt][2] + bv2.x, p3 = c[mt][nt][3] + bv2.y;
            if (mode == 0) {
                __nv_bfloat16 *dh, *dl;
                if (z == 0)      { dh = g_qhi; dl = g_qlo; }
                else if (z == 1) { dh = g_khi; dl = g_klo; }
                else             { dh = g_vhi; dl = g_vlo; }
                int h = n >> 6, d = n & 63;
                int bb0 = r >> 11, s0 = r & 2047;
                int bb1 = (r + 8) >> 11, s1 = (r + 8) & 2047;
                size_t i0 = (((size_t)bb0 * H_ + h) * S_ + s0) * HD_ + d;
                size_t i1 = (((size_t)bb1 * H_ + h) * S_ + s1) * HD_ + d;
                uint32_t h01 = packbf(p0, p1);
                uint32_t l01 = packbf(p0 - bflo(h01), p1 - bfhi(h01));
                uint32_t h23 = packbf(p2, p3);
                uint32_t l23 = packbf(p2 - bflo(h23), p3 - bfhi(h23));
                *(uint32_t*)&dh[i0] = h01; *(uint32_t*)&dl[i0] = l01;
                *(uint32_t*)&dh[i1] = h23; *(uint32_t*)&dl[i1] = l23;
            } else {
                float2 v0 = {p0, p1}, v1 = {p2, p3};
                *(float2*)&outp[(size_t)r * EMB_ + n] = v0;
                *(float2*)&outp[(size_t)(r + 8) * EMB_ + n] = v1;
            }
        }
    }
}

// ---------------- mma.sync causal flash attention ---------------------------
// CTA: 128 q-rows x 64-key stages, 8 warps x 16 q-rows, bf16 3-term split.
// Diagonal pruning: on the two straddling key-tiles each warp computes only
// the key groups it can actually see.
constexpr int ASTR   = 144;
constexpr int AQMAT  = 128 * ASTR;                  // 18432
constexpr int AKMAT  = 64 * ASTR;                   // 9216
constexpr int ASTAGE = 4 * AKMAT;                   // 36864
constexpr int ATTN_SMEM = 2 * AQMAT + 2 * ASTAGE;   // 110592 -> 2 CTAs/SM

__device__ __forceinline__ void akv_load(
    uint32_t base, const __nv_bfloat16* Kh, const __nv_bfloat16* Kl,
    const __nv_bfloat16* Vh, const __nv_bfloat16* Vl, int kt, int tid)
{
    #pragma unroll
    for (int i = tid; i < 2048; i += 256) {
        int mat = i >> 9;
        int r   = (i >> 3) & 63;
        int c   = i & 7;
        const __nv_bfloat16* m =
            (mat == 0) ? Kh : (mat == 1) ? Kl : (mat == 2) ? Vh : Vl;
        cpa16(base + mat * AKMAT + r * ASTR + c * 16,
              m + (size_t)(kt * 64 + r) * HD_ + c * 8);
    }
}

__global__ __launch_bounds__(256, 2) void attn_mma_kernel()
{
    extern __shared__ char smem[];
    const uint32_t sb = smem_u32(smem);
    const int tid = threadIdx.x, wid = tid >> 5, lane = tid & 31;
    const int qt = blockIdx.x, bh = blockIdx.y;
    const size_t off = (size_t)bh * S_ * HD_;
    const __nv_bfloat16 *Qh = g_qhi + off, *Ql = g_qlo + off;
    const __nv_bfloat16 *Kh = g_khi + off, *Kl = g_klo + off;
    const __nv_bfloat16 *Vh = g_vhi + off, *Vl = g_vlo + off;
    const int ntiles = 2 * qt + 2;

    #pragma unroll
    for (int i = tid; i < 2048; i += 256) {
        int mat = i >> 10, r = (i >> 3) & 127, c = i & 7;
        const __nv_bfloat16* m = mat ? Ql : Qh;
        cpa16(sb + mat * AQMAT + r * ASTR + c * 16,
              m + (size_t)(qt * 128 + r) * HD_ + c * 8);
    }
    akv_load(sb + 2 * AQMAT, Kh, Kl, Vh, Vl, 0, tid);
    CPA_COMMIT();
    akv_load(sb + 2 * AQMAT + ASTAGE, Kh, Kl, Vh, Vl, 1, tid);
    CPA_COMMIT();

    const int a_row = wid * 16 + (lane & 7) + ((lane >> 3) & 1) * 8;
    const int a_kc2 = ((lane >> 4) & 1) * 16;
    const int b_row = (lane & 7) + ((lane >> 4) & 1) * 8;
    const int b_kc2 = ((lane >> 3) & 1) * 16;
    const int v_row = (lane & 7) + ((lane >> 3) & 1) * 8;
    const int v_cc2 = ((lane >> 4) & 1) * 16;
    const int row0g = qt * 128 + wid * 16 + (lane >> 2);

    float O[8][4] = {};
    float m0 = -1e30f, m1 = -1e30f, l0 = 0.0f, l1 = 0.0f;
    const float sc = 0.125f * 1.44269504f;   // scale * log2(e)

    for (int kt = 0; kt < ntiles; ++kt) {
        CPA_WAIT1();
        __syncthreads();
        const uint32_t st = sb + 2 * AQMAT + (kt & 1) * ASTAGE;

        // diagonal pruning: key groups this warp actually needs (of 4)
        int gmax = 4;
        if (kt == 2 * qt + 1)      gmax = (wid > 3) ? (wid - 3) : 0;
        else if (kt == 2 * qt)     gmax = (wid < 3) ? (wid + 1) : 4;
        const int jmax = 2 * gmax;

        // ---- S = Q K^T (3-term split) ----
        float S[8][4];
        #pragma unroll
        for (int j = 0; j < 8; ++j) { S[j][0]=0; S[j][1]=0; S[j][2]=0; S[j][3]=0; }
        if (gmax > 0) {
            #pragma unroll
            for (int ks = 0; ks < 4; ++ks) {
                uint32_t qaddr = sb + a_row * ASTR + ks * 32 + a_kc2;
                uint32_t ah[4], al[4];
                LDSM4(ah[0], ah[1], ah[2], ah[3], qaddr);
                LDSM4(al[0], al[1], al[2], al[3], qaddr + AQMAT);
                for (int g = 0; g < gmax; ++g) {
                    uint32_t kaddr = st + (g * 16 + b_row) * ASTR + ks * 32 + b_kc2;
                    uint32_t kh[4], kl[4];
                    LDSM4(kh[0], kh[1], kh[2], kh[3], kaddr);
                    LDSM4(kl[0], kl[1], kl[2], kl[3], kaddr + AKMAT);
                    MMA16816(S[2 * g],     ah, kh[0], kh[1]);
                    MMA16816(S[2 * g],     ah, kl[0], kl[1]);
                    MMA16816(S[2 * g],     al, kh[0], kh[1]);
                    MMA16816(S[2 * g + 1], ah, kh[2], kh[3]);
                    MMA16816(S[2 * g + 1], ah, kl[2], kl[3]);
                    MMA16816(S[2 * g + 1], al, kh[2], kh[3]);
                }
            }
        }

        // ---- scale (log2 domain) + causal mask on straddling tiles ----
        for (int j = 0; j < jmax; ++j) {
            S[j][0] *= sc; S[j][1] *= sc; S[j][2] *= sc; S[j][3] *= sc;
        }
        if (kt >= 2 * qt) {
            for (int j = 0; j < jmax; ++j) {
                int col = kt * 64 + j * 8 + (lane & 3) * 2;
                if (col     > row0g)     S[j][0] = -1e30f;
                if (col + 1 > row0g)     S[j][1] = -1e30f;
                if (col     > row0g + 8) S[j][2] = -1e30f;
                if (col + 1 > row0g + 8) S[j][3] = -1e30f;
            }
        }

        // ---- online softmax ----
        float mx0 = -1e30f, mx1 = -1e30f;
        for (int j = 0; j < jmax; ++j) {
            mx0 = fmaxf(mx0, fmaxf(S[j][0], S[j][1]));
            mx1 = fmaxf(mx1, fmaxf(S[j][2], S[j][3]));
        }
        mx0 = fmaxf(mx0, __shfl_xor_sync(0xffffffffu, mx0, 1));
        mx0 = fmaxf(mx0, __shfl_xor_sync(0xffffffffu, mx0, 2));
        mx1 = fmaxf(mx1, __shfl_xor_sync(0xffffffffu, mx1, 1));
        mx1 = fmaxf(mx1, __shfl_xor_sync(0xffffffffu, mx1, 2));
        float nm0 = fmaxf(m0, mx0), nm1 = fmaxf(m1, mx1);
        float f0 = ex2(m0 - nm0), f1 = ex2(m1 - nm1);
        m0 = nm0; m1 = nm1;
        float s0 = 0.0f, s1 = 0.0f;
        for (int j = 0; j < jmax; ++j) {
            S[j][0] = ex2(S[j][0] - nm0); S[j][1] = ex2(S[j][1] - nm0);
            S[j][2] = ex2(S[j][2] - nm1); S[j][3] = ex2(S[j][3] - nm1);
            s0 += S[j][0] + S[j][1];
            s1 += S[j][2] + S[j][3];
        }
        s0 += __shfl_xor_sync(0xffffffffu, s0, 1);
        s0 += __shfl_xor_sync(0xffffffffu, s0, 2);
        s1 += __shfl_xor_sync(0xffffffffu, s1, 1);
        s1 += __shfl_xor_sync(0xffffffffu, s1, 2);
        l0 = l0 * f0 + s0; l1 = l1 * f1 + s1;
        #pragma unroll
        for (int j = 0; j < 8; ++j) {
            O[j][0] *= f0; O[j][1] *= f0; O[j][2] *= f1; O[j][3] *= f1;
        }

        // ---- O += P V (3-term split; only live key groups) ----
        for (int ks = 0; ks < gmax; ++ks) {
            uint32_t ph[4], pl[4];
            ph[0] = packbf(S[2 * ks][0],     S[2 * ks][1]);
            ph[1] = packbf(S[2 * ks][2],     S[2 * ks][3]);
            ph[2] = packbf(S[2 * ks + 1][0], S[2 * ks + 1][1]);
            ph[3] = packbf(S[2 * ks + 1][2], S[2 * ks + 1][3]);
            pl[0] = packbf(S[2 * ks][0]     - bflo(ph[0]), S[2 * ks][1]     - bfhi(ph[0]));
            pl[1] = packbf(S[2 * ks][2]     - bflo(ph[1]), S[2 * ks][3]     - bfhi(ph[1]));
            pl[2] = packbf(S[2 * ks + 1][0] - bflo(ph[2]), S[2 * ks + 1][1] - bfhi(ph[2]));
            pl[3] = packbf(S[2 * ks + 1][2] - bflo(ph[3]), S[2 * ks + 1][3] - bfhi(ph[3]));
            #pragma unroll
            for (int g = 0; g < 4; ++g) {
                uint32_t vaddr = st + 2 * AKMAT + (ks * 16 + v_row) * ASTR
                               + g * 32 + v_cc2;
                uint32_t vh[4], vl[4];
                LDSM4T(vh[0], vh[1], vh[2], vh[3], vaddr);
                LDSM4T(vl[0], vl[1], vl[2], vl[3], vaddr + AKMAT);
                MMA16816(O[2 * g],     ph, vh[0], vh[1]);
                MMA16816(O[2 * g],     ph, vl[0], vl[1]);
                MMA16816(O[2 * g],     pl, vh[0], vh[1]);
                MMA16816(O[2 * g + 1], ph, vh[2], vh[3]);
                MMA16816(O[2 * g + 1], ph, vl[2], vl[3]);
                MMA16816(O[2 * g + 1], pl, vh[2], vh[3]);
            }
        }

        __syncthreads();
        if (kt + 2 < ntiles) {
            akv_load(sb + 2 * AQMAT + (kt & 1) * ASTAGE, Kh, Kl, Vh, Vl, kt + 2, tid);
            CPA_COMMIT();
        } else {
            CPA_COMMIT();
        }
    }

    // ---- epilogue: normalize, split bf16 hi/lo, write [B,S,EMB] ----
    const float inv0 = 1.0f / l0, inv1 = 1.0f / l1;
    const int b = bh >> 4, h = bh & 15;
    const int r0 = qt * 128 + wid * 16 + (lane >> 2);
    const int cc = (lane & 3) * 2;
    #pragma unroll
    for (int j = 0; j < 8; ++j) {
        float p0 = O[j][0] * inv0, p1 = O[j][1] * inv0;
        float p2 = O[j][2] * inv1, p3 = O[j][3] * inv1;
        size_t i0 = ((size_t)b * S_ + r0) * EMB_ + h * 64 + j * 8 + cc;
        size_t i1 = i0 + (size_t)8 * EMB_;
        uint32_t h01 = packbf(p0, p1);
        uint32_t l01 = packbf(p0 - bflo(h01), p1 - bfhi(h01));
        uint32_t h23 = packbf(p2, p3);
        uint32_t l23 = packbf(p2 - bflo(h23), p3 - bfhi(h23));
        *(uint32_t*)&g_ahi[i0] = h01; *(uint32_t*)&g_alo[i0] = l01;
        *(uint32_t*)&g_ahi[i1] = h23; *(uint32_t*)&g_alo[i1] = l23;
    }
}

// ---------------- launch ---------------------------------------------------
extern "C" void kernel_launch(void* const* d_in, const int* in_sizes, int n_in,
                              void* d_out, int out_size)
{
    const float* x  = (const float*)d_in[0];
    const float* Wq = (const float*)d_in[1];
    const float* bq = (const float*)d_in[2];
    const float* Wk = (const float*)d_in[3];
    const float* bk = (const float*)d_in[4];
    const float* Wv = (const float*)d_in[5];
    const float* bv = (const float*)d_in[6];
    const float* Wo = (const float*)d_in[7];
    const float* bo = (const float*)d_in[8];
    float* out = (float*)d_out;

    cudaFuncSetAttribute(gemm_mma_kernel,
                         cudaFuncAttributeMaxDynamicSharedMemorySize, GEMM_SMEM);
    cudaFuncSetAttribute(attn_mma_kernel,
                         cudaFuncAttributeMaxDynamicSharedMemorySize, ATTN_SMEM);

    const int n4x = M_ * EMB_ / 4;
    const int n4w = EMB_ * EMB_ / 4;
    conv_split_x<<<n4x / 256, 256>>>(x, n4x);
    conv_split_w<<<dim3(n4w / 256, 4), 256>>>(Wq, Wk, Wv, Wo);

    // QKV projections (mma.sync) -> bf16 hi/lo Q/K/V
    gemm_mma_kernel<<<dim3(EMB_ / 128, M_ / 128, 3), 256, GEMM_SMEM>>>(
        bq, bk, bv, nullptr, 0);

    // causal attention (mma.sync flash, 64-key stages, diagonal pruning)
    attn_mma_kernel<<<dim3(S_ / 128, B_ * H_), 256, ATTN_SMEM>>>();

    // output projection (mma.sync)
    gemm_mma_kernel<<<dim3(EMB_ / 128, M_ / 128, 1), 256, GEMM_SMEM>>>(
        bo, nullptr, nullptr, out, 1);
}

// round 8
// speedup vs baseline: 1.6064x; 1.6064x over previous
#include <cuda_runtime.h>
#include <cuda_bf16.h>
#include <math.h>
#include <stdint.h>

#define B_   4
#define S_   2048
#define EMB_ 1024
#define H_   16
#define HD_  64
#define M_   (B_ * S_)   // 8192

// ---- ptx helpers (mma.sync / ldmatrix / cp.async) — baseline sm_103 legal --
__device__ __forceinline__ uint32_t smem_u32(const void* p) {
    uint32_t a;
    asm("{ .reg .u64 t; cvta.to.shared.u64 t, %1; cvt.u32.u64 %0, t; }"
        : "=r"(a) : "l"(p));
    return a;
}
__device__ __forceinline__ void cpa16(uint32_t dst, const void* src) {
    asm volatile("cp.async.cg.shared.global [%0], [%1], 16;" :: "r"(dst), "l"(src) : "memory");
}
#define CPA_COMMIT() asm volatile("cp.async.commit_group;" ::: "memory")
#define CPA_WAIT1()  asm volatile("cp.async.wait_group 1;"  ::: "memory")

#define LDSM4(r0, r1, r2, r3, addr) \
    asm volatile("ldmatrix.sync.aligned.m8n8.x4.shared.b16 {%0,%1,%2,%3}, [%4];" \
        : "=r"(r0), "=r"(r1), "=r"(r2), "=r"(r3) : "r"(addr))
#define LDSM4T(r0, r1, r2, r3, addr) \
    asm volatile("ldmatrix.sync.aligned.m8n8.x4.trans.shared.b16 {%0,%1,%2,%3}, [%4];" \
        : "=r"(r0), "=r"(r1), "=r"(r2), "=r"(r3) : "r"(addr))

#define MMA16816(c, a, b0, b1) \
    asm volatile("mma.sync.aligned.m16n8k16.row.col.f32.bf16.bf16.f32 " \
        "{%0,%1,%2,%3},{%4,%5,%6,%7},{%8,%9},{%0,%1,%2,%3};" \
        : "+f"((c)[0]), "+f"((c)[1]), "+f"((c)[2]), "+f"((c)[3]) \
        : "r"((a)[0]), "r"((a)[1]), "r"((a)[2]), "r"((a)[3]), "r"(b0), "r"(b1))

__device__ __forceinline__ uint32_t packbf(float lo, float hi) {
    uint32_t r;
    asm("cvt.rn.bf16x2.f32 %0, %1, %2;" : "=r"(r) : "f"(hi), "f"(lo));
    return r;
}
__device__ __forceinline__ float bflo(uint32_t p) { return __uint_as_float(p << 16); }
__device__ __forceinline__ float bfhi(uint32_t p) { return __uint_as_float(p & 0xffff0000u); }
__device__ __forceinline__ float ex2(float x) {
    float r; asm("ex2.approx.f32 %0, %1;" : "=f"(r) : "f"(x)); return r;
}

// ---------------- scratch (device globals; no allocation allowed) ----------
__device__ __align__(16) __nv_bfloat16 g_xhi[(size_t)M_ * EMB_];
__device__ __align__(16) __nv_bfloat16 g_xlo[(size_t)M_ * EMB_];
__device__ __align__(16) __nv_bfloat16 g_whi[(size_t)4 * EMB_ * EMB_];
__device__ __align__(16) __nv_bfloat16 g_wlo[(size_t)4 * EMB_ * EMB_];
__device__ __align__(16) __nv_bfloat16 g_qhi[(size_t)M_ * EMB_];
__device__ __align__(16) __nv_bfloat16 g_qlo[(size_t)M_ * EMB_];
__device__ __align__(16) __nv_bfloat16 g_khi[(size_t)M_ * EMB_];
__device__ __align__(16) __nv_bfloat16 g_klo[(size_t)M_ * EMB_];
__device__ __align__(16) __nv_bfloat16 g_vhi[(size_t)M_ * EMB_];
__device__ __align__(16) __nv_bfloat16 g_vlo[(size_t)M_ * EMB_];
__device__ __align__(16) __nv_bfloat16 g_ahi[(size_t)M_ * EMB_];
__device__ __align__(16) __nv_bfloat16 g_alo[(size_t)M_ * EMB_];

// ---------------- fp32 -> bf16 hi/lo split ----------------------------------
__global__ __launch_bounds__(256) void conv_split_x(
    const float* __restrict__ src, int n4)
{
    int i = blockIdx.x * 256 + threadIdx.x;
    if (i >= n4) return;
    float4 v = ((const float4*)src)[i];
    uint32_t h01 = packbf(v.x, v.y), h23 = packbf(v.z, v.w);
    uint32_t l01 = packbf(v.x - bflo(h01), v.y - bfhi(h01));
    uint32_t l23 = packbf(v.z - bflo(h23), v.w - bfhi(h23));
    ((uint32_t*)g_xhi)[2 * i] = h01; ((uint32_t*)g_xhi)[2 * i + 1] = h23;
    ((uint32_t*)g_xlo)[2 * i] = l01; ((uint32_t*)g_xlo)[2 * i + 1] = l23;
}
__global__ __launch_bounds__(256) void conv_split_w(
    const float* __restrict__ w0, const float* __restrict__ w1,
    const float* __restrict__ w2, const float* __restrict__ w3)
{
    const int which = blockIdx.y;
    const float* src = (which == 0) ? w0 : (which == 1) ? w1 : (which == 2) ? w2 : w3;
    __nv_bfloat16* hi = g_whi + (size_t)which * EMB_ * EMB_;
    __nv_bfloat16* lo = g_wlo + (size_t)which * EMB_ * EMB_;
    int i = blockIdx.x * 256 + threadIdx.x;
    float4 v = ((const float4*)src)[i];
    uint32_t h01 = packbf(v.x, v.y), h23 = packbf(v.z, v.w);
    uint32_t l01 = packbf(v.x - bflo(h01), v.y - bfhi(h01));
    uint32_t l23 = packbf(v.z - bflo(h23), v.w - bfhi(h23));
    ((uint32_t*)hi)[2 * i] = h01; ((uint32_t*)hi)[2 * i + 1] = h23;
    ((uint32_t*)lo)[2 * i] = l01; ((uint32_t*)lo)[2 * i + 1] = l23;
}

// ---------------- mma.sync GEMM: D = A @ W^T + bias (R5 config) -------------
constexpr int GSTRIDE = 144;
constexpr int GMAT    = 128 * GSTRIDE;             // 18432
constexpr int GSTAGE  = 4 * GMAT;                  // 73728
constexpr int GEMM_SMEM = 2 * GSTAGE;              // 147456

__device__ __forceinline__ void gload_chunk(
    uint32_t sbase, const __nv_bfloat16* Ahi, const __nv_bfloat16* Alo,
    const __nv_bfloat16* Bhi, const __nv_bfloat16* Blo,
    int row0, int col0, int k0, int tid)
{
    #pragma unroll
    for (int i = tid; i < 4096; i += 256) {
        int mat = i >> 10;
        int r   = (i >> 3) & 127;
        int c   = i & 7;
        uint32_t dst = sbase + mat * GMAT + r * GSTRIDE + c * 16;
        const __nv_bfloat16* m =
            (mat == 0) ? Ahi : (mat == 1) ? Alo : (mat == 2) ? Bhi : Blo;
        int gr = ((mat < 2) ? row0 : col0) + r;
        cpa16(dst, m + (size_t)gr * EMB_ + k0 + c * 8);
    }
    CPA_COMMIT();
}

__global__ __launch_bounds__(256) void gemm_mma_kernel(
    const float* __restrict__ bq, const float* __restrict__ bk,
    const float* __restrict__ bv, float* __restrict__ outp, int mode)
{
    extern __shared__ char smem[];
    const uint32_t sb = smem_u32(smem);
    const int tid = threadIdx.x, wid = tid >> 5, lane = tid & 31;
    const int row0 = blockIdx.y * 128, col0 = blockIdx.x * 128;
    const int z = blockIdx.z;

    const __nv_bfloat16 *Ahi, *Alo, *Bhi, *Blo;
    const float* bias;
    if (mode == 0) {
        Ahi = g_xhi; Alo = g_xlo;
        Bhi = g_whi + (size_t)z * EMB_ * EMB_;
        Blo = g_wlo + (size_t)z * EMB_ * EMB_;
        bias = (z == 0) ? bq : (z == 1) ? bk : bv;
    } else {
        Ahi = g_ahi; Alo = g_alo;
        Bhi = g_whi + (size_t)3 * EMB_ * EMB_;
        Blo = g_wlo + (size_t)3 * EMB_ * EMB_;
        bias = bq;
    }

    const int wm = (wid & 1) * 64;
    const int wn = (wid >> 1) * 32;

    float c[4][4][4] = {};

    gload_chunk(sb,          Ahi, Alo, Bhi, Blo, row0, col0, 0,  tid);
    gload_chunk(sb + GSTAGE, Ahi, Alo, Bhi, Blo, row0, col0, 64, tid);

    const int a_row = wm + (lane & 7) + ((lane >> 3) & 1) * 8;
    const int a_kc  = ((lane >> 4) & 1) * 8;
    const int b_row = wn + (lane & 7) + ((lane >> 4) & 1) * 8;
    const int b_kc  = ((lane >> 3) & 1) * 8;

    for (int ch = 0; ch < 16; ++ch) {
        const int s = ch & 1;
        CPA_WAIT1();
        __syncthreads();
        const uint32_t st = sb + s * GSTAGE;

        #pragma unroll
        for (int kk = 0; kk < 64; kk += 16) {
            uint32_t bh[2][4], bl[2][4];
            #pragma unroll
            for (int pt = 0; pt < 2; ++pt) {
                uint32_t addr = st + 2 * GMAT + (b_row + pt * 16) * GSTRIDE
                              + (kk + b_kc) * 2;
                LDSM4(bh[pt][0], bh[pt][1], bh[pt][2], bh[pt][3], addr);
                LDSM4(bl[pt][0], bl[pt][1], bl[pt][2], bl[pt][3], addr + GMAT);
            }
            #pragma unroll
            for (int mt = 0; mt < 4; ++mt) {
                uint32_t addr = st + (a_row + mt * 16) * GSTRIDE
                              + (kk + a_kc) * 2;
                uint32_t ah[4], al[4];
                LDSM4(ah[0], ah[1], ah[2], ah[3], addr);
                LDSM4(al[0], al[1], al[2], al[3], addr + GMAT);
                #pragma unroll
                for (int nt = 0; nt < 4; ++nt) {
                    const int pt = nt >> 1, hf = (nt & 1) * 2;
                    MMA16816(c[mt][nt], ah, bh[pt][hf], bh[pt][hf + 1]);
                    MMA16816(c[mt][nt], ah, bl[pt][hf], bl[pt][hf + 1]);
                    MMA16816(c[mt][nt], al, bh[pt][hf], bh[pt][hf + 1]);
                }
            }
        }
        __syncthreads();
        if (ch + 2 < 16)
            gload_chunk(sb + s * GSTAGE, Ahi, Alo, Bhi, Blo,
                        row0, col0, (ch + 2) * 64, tid);
        else
            CPA_COMMIT();
    }

    #pragma unroll
    for (int mt = 0; mt < 4; ++mt) {
        #pragma unroll
        for (int nt = 0; nt < 4; ++nt) {
            int r = row0 + wm + mt * 16 + (lane >> 2);
            int n = col0 + wn + nt * 8 + (lane & 3) * 2;
            float2 bv2 = *(const float2*)&bias[n];
            float p0 = c[mt][nt][0] + bv2.x, p1 = c[mt][nt][1] + bv2.y;
            float p2 = c[mt][nt][2] + bv2.x, p3 = c[mt][nt][3] + bv2.y;
            if (mode == 0) {
                __nv_bfloat16 *dh, *dl;
                if (z == 0)      { dh = g_qhi; dl = g_qlo; }
                else if (z == 1) { dh = g_khi; dl = g_klo; }
                else             { dh = g_vhi; dl = g_vlo; }
                int h = n >> 6, d = n & 63;
                int bb0 = r >> 11, s0 = r & 2047;
                int bb1 = (r + 8) >> 11, s1 = (r + 8) & 2047;
                size_t i0 = (((size_t)bb0 * H_ + h) * S_ + s0) * HD_ + d;
                size_t i1 = (((size_t)bb1 * H_ + h) * S_ + s1) * HD_ + d;
                uint32_t h01 = packbf(p0, p1);
                uint32_t l01 = packbf(p0 - bflo(h01), p1 - bfhi(h01));
                uint32_t h23 = packbf(p2, p3);
                uint32_t l23 = packbf(p2 - bflo(h23), p3 - bfhi(h23));
                *(uint32_t*)&dh[i0] = h01; *(uint32_t*)&dl[i0] = l01;
                *(uint32_t*)&dh[i1] = h23; *(uint32_t*)&dl[i1] = l23;
            } else {
                float2 v0 = {p0, p1}, v1 = {p2, p3};
                *(float2*)&outp[(size_t)r * EMB_ + n] = v0;
                *(float2*)&outp[(size_t)(r + 8) * EMB_ + n] = v1;
            }
        }
    }
}

// ---------------- mma.sync causal flash attention (R5 config) ---------------
constexpr int ASTR   = 144;
constexpr int AQMAT  = 128 * ASTR;                  // 18432
constexpr int AKMAT  = 64 * ASTR;                   // 9216
constexpr int ASTAGE = 4 * AKMAT;                   // 36864
constexpr int ATTN_SMEM = 2 * AQMAT + 2 * ASTAGE;   // 110592

__device__ __forceinline__ void akv_load(
    uint32_t base, const __nv_bfloat16* Kh, const __nv_bfloat16* Kl,
    const __nv_bfloat16* Vh, const __nv_bfloat16* Vl, int kt, int tid)
{
    #pragma unroll
    for (int i = tid; i < 2048; i += 256) {
        int mat = i >> 9;
        int r   = (i >> 3) & 63;
        int c   = i & 7;
        const __nv_bfloat16* m =
            (mat == 0) ? Kh : (mat == 1) ? Kl : (mat == 2) ? Vh : Vl;
        cpa16(base + mat * AKMAT + r * ASTR + c * 16,
              m + (size_t)(kt * 64 + r) * HD_ + c * 8);
    }
}

__global__ __launch_bounds__(256) void attn_mma_kernel()
{
    extern __shared__ char smem[];
    const uint32_t sb = smem_u32(smem);
    const int tid = threadIdx.x, wid = tid >> 5, lane = tid & 31;
    const int qt = (S_ / 128 - 1) - blockIdx.y;   // heavy tiles dispatch first
    const int bh = blockIdx.x;
    const size_t off = (size_t)bh * S_ * HD_;
    const __nv_bfloat16 *Qh = g_qhi + off, *Ql = g_qlo + off;
    const __nv_bfloat16 *Kh = g_khi + off, *Kl = g_klo + off;
    const __nv_bfloat16 *Vh = g_vhi + off, *Vl = g_vlo + off;
    const int ntiles = 2 * qt + 2;

    #pragma unroll
    for (int i = tid; i < 2048; i += 256) {
        int mat = i >> 10, r = (i >> 3) & 127, c = i & 7;
        const __nv_bfloat16* m = mat ? Ql : Qh;
        cpa16(sb + mat * AQMAT + r * ASTR + c * 16,
              m + (size_t)(qt * 128 + r) * HD_ + c * 8);
    }
    akv_load(sb + 2 * AQMAT, Kh, Kl, Vh, Vl, 0, tid);
    CPA_COMMIT();
    akv_load(sb + 2 * AQMAT + ASTAGE, Kh, Kl, Vh, Vl, 1, tid);
    CPA_COMMIT();

    const int a_row = wid * 16 + (lane & 7) + ((lane >> 3) & 1) * 8;
    const int a_kc2 = ((lane >> 4) & 1) * 16;
    const int b_row = (lane & 7) + ((lane >> 4) & 1) * 8;
    const int b_kc2 = ((lane >> 3) & 1) * 16;
    const int v_row = (lane & 7) + ((lane >> 3) & 1) * 8;
    const int v_cc2 = ((lane >> 4) & 1) * 16;
    const int row0g = qt * 128 + wid * 16 + (lane >> 2);

    float O[8][4] = {};
    float m0 = -1e30f, m1 = -1e30f, l0 = 0.0f, l1 = 0.0f;
    const float sc = 0.125f * 1.44269504f;   // scale * log2(e)

    for (int kt = 0; kt < ntiles; ++kt) {
        CPA_WAIT1();
        __syncthreads();
        const uint32_t st = sb + 2 * AQMAT + (kt & 1) * ASTAGE;

        // ---- S = Q K^T (3-term split, fully static unroll) ----
        float S[8][4] = {};
        #pragma unroll
        for (int ks = 0; ks < 4; ++ks) {
            uint32_t qaddr = sb + a_row * ASTR + ks * 32 + a_kc2;
            uint32_t ah[4], al[4];
            LDSM4(ah[0], ah[1], ah[2], ah[3], qaddr);
            LDSM4(al[0], al[1], al[2], al[3], qaddr + AQMAT);
            #pragma unroll
            for (int g = 0; g < 4; ++g) {
                uint32_t kaddr = st + (g * 16 + b_row) * ASTR + ks * 32 + b_kc2;
                uint32_t kh[4], kl[4];
                LDSM4(kh[0], kh[1], kh[2], kh[3], kaddr);
                LDSM4(kl[0], kl[1], kl[2], kl[3], kaddr + AKMAT);
                MMA16816(S[2 * g],     ah, kh[0], kh[1]);
                MMA16816(S[2 * g],     ah, kl[0], kl[1]);
                MMA16816(S[2 * g],     al, kh[0], kh[1]);
                MMA16816(S[2 * g + 1], ah, kh[2], kh[3]);
                MMA16816(S[2 * g + 1], ah, kl[2], kl[3]);
                MMA16816(S[2 * g + 1], al, kh[2], kh[3]);
            }
        }

        // ---- scale (log2 domain) + causal mask ----
        #pragma unroll
        for (int j = 0; j < 8; ++j) {
            S[j][0] *= sc; S[j][1] *= sc; S[j][2] *= sc; S[j][3] *= sc;
        }
        if (kt * 64 + 63 > qt * 128 + wid * 16) {
            #pragma unroll
            for (int j = 0; j < 8; ++j) {
                int col = kt * 64 + j * 8 + (lane & 3) * 2;
                if (col     > row0g)     S[j][0] = -1e30f;
                if (col + 1 > row0g)     S[j][1] = -1e30f;
                if (col     > row0g + 8) S[j][2] = -1e30f;
                if (col + 1 > row0g + 8) S[j][3] = -1e30f;
            }
        }

        // ---- online softmax ----
        float mx0 = -1e30f, mx1 = -1e30f;
        #pragma unroll
        for (int j = 0; j < 8; ++j) {
            mx0 = fmaxf(mx0, fmaxf(S[j][0], S[j][1]));
            mx1 = fmaxf(mx1, fmaxf(S[j][2], S[j][3]));
        }
        mx0 = fmaxf(mx0, __shfl_xor_sync(0xffffffffu, mx0, 1));
        mx0 = fmaxf(mx0, __shfl_xor_sync(0xffffffffu, mx0, 2));
        mx1 = fmaxf(mx1, __shfl_xor_sync(0xffffffffu, mx1, 1));
        mx1 = fmaxf(mx1, __shfl_xor_sync(0xffffffffu, mx1, 2));
        float nm0 = fmaxf(m0, mx0), nm1 = fmaxf(m1, mx1);
        float f0 = ex2(m0 - nm0), f1 = ex2(m1 - nm1);
        m0 = nm0; m1 = nm1;
        float s0 = 0.0f, s1 = 0.0f;
        #pragma unroll
        for (int j = 0; j < 8; ++j) {
            S[j][0] = ex2(S[j][0] - nm0); S[j][1] = ex2(S[j][1] - nm0);
            S[j][2] = ex2(S[j][2] - nm1); S[j][3] = ex2(S[j][3] - nm1);
            s0 += S[j][0] + S[j][1];
            s1 += S[j][2] + S[j][3];
        }
        s0 += __shfl_xor_sync(0xffffffffu, s0, 1);
        s0 += __shfl_xor_sync(0xffffffffu, s0, 2);
        s1 += __shfl_xor_sync(0xffffffffu, s1, 1);
        s1 += __shfl_xor_sync(0xffffffffu, s1, 2);
        l0 = l0 * f0 + s0; l1 = l1 * f1 + s1;
        #pragma unroll
        for (int j = 0; j < 8; ++j) {
            O[j][0] *= f0; O[j][1] *= f0; O[j][2] *= f1; O[j][3] *= f1;
        }

        // ---- O += P V (3-term split, fully static unroll) ----
        #pragma unroll
        for (int ks = 0; ks < 4; ++ks) {
            uint32_t ph[4], pl[4];
            ph[0] = packbf(S[2 * ks][0],     S[2 * ks][1]);
            ph[1] = packbf(S[2 * ks][2],     S[2 * ks][3]);
            ph[2] = packbf(S[2 * ks + 1][0], S[2 * ks + 1][1]);
            ph[3] = packbf(S[2 * ks + 1][2], S[2 * ks + 1][3]);
            pl[0] = packbf(S[2 * ks][0]     - bflo(ph[0]), S[2 * ks][1]     - bfhi(ph[0]));
            pl[1] = packbf(S[2 * ks][2]     - bflo(ph[1]), S[2 * ks][3]     - bfhi(ph[1]));
            pl[2] = packbf(S[2 * ks + 1][0] - bflo(ph[2]), S[2 * ks + 1][1] - bfhi(ph[2]));
            pl[3] = packbf(S[2 * ks + 1][2] - bflo(ph[3]), S[2 * ks + 1][3] - bfhi(ph[3]));
            #pragma unroll
            for (int g = 0; g < 4; ++g) {
                uint32_t vaddr = st + 2 * AKMAT + (ks * 16 + v_row) * ASTR
                               + g * 32 + v_cc2;
                uint32_t vh[4], vl[4];
                LDSM4T(vh[0], vh[1], vh[2], vh[3], vaddr);
                LDSM4T(vl[0], vl[1], vl[2], vl[3], vaddr + AKMAT);
                MMA16816(O[2 * g],     ph, vh[0], vh[1]);
                MMA16816(O[2 * g],     ph, vl[0], vl[1]);
                MMA16816(O[2 * g],     pl, vh[0], vh[1]);
                MMA16816(O[2 * g + 1], ph, vh[2], vh[3]);
                MMA16816(O[2 * g + 1], ph, vl[2], vl[3]);
                MMA16816(O[2 * g + 1], pl, vh[2], vh[3]);
            }
        }

        __syncthreads();
        if (kt + 2 < ntiles) {
            akv_load(sb + 2 * AQMAT + (kt & 1) * ASTAGE, Kh, Kl, Vh, Vl, kt + 2, tid);
            CPA_COMMIT();
        } else {
            CPA_COMMIT();
        }
    }

    // ---- epilogue: normalize, split bf16 hi/lo, write [B,S,EMB] ----
    const float inv0 = 1.0f / l0, inv1 = 1.0f / l1;
    const int b = bh >> 4, h = bh & 15;
    const int r0 = qt * 128 + wid * 16 + (lane >> 2);
    const int cc = (lane & 3) * 2;
    #pragma unroll
    for (int j = 0; j < 8; ++j) {
        float p0 = O[j][0] * inv0, p1 = O[j][1] * inv0;
        float p2 = O[j][2] * inv1, p3 = O[j][3] * inv1;
        size_t i0 = ((size_t)b * S_ + r0) * EMB_ + h * 64 + j * 8 + cc;
        size_t i1 = i0 + (size_t)8 * EMB_;
        uint32_t h01 = packbf(p0, p1);
        uint32_t l01 = packbf(p0 - bflo(h01), p1 - bfhi(h01));
        uint32_t h23 = packbf(p2, p3);
        uint32_t l23 = packbf(p2 - bflo(h23), p3 - bfhi(h23));
        *(uint32_t*)&g_ahi[i0] = h01; *(uint32_t*)&g_alo[i0] = l01;
        *(uint32_t*)&g_ahi[i1] = h23; *(uint32_t*)&g_alo[i1] = l23;
    }
}

// ---------------- launch ---------------------------------------------------
extern "C" void kernel_launch(void* const* d_in, const int* in_sizes, int n_in,
                              void* d_out, int out_size)
{
    const float* x  = (const float*)d_in[0];
    const float* Wq = (const float*)d_in[1];
    const float* bq = (const float*)d_in[2];
    const float* Wk = (const float*)d_in[3];
    const float* bk = (const float*)d_in[4];
    const float* Wv = (const float*)d_in[5];
    const float* bv = (const float*)d_in[6];
    const float* Wo = (const float*)d_in[7];
    const float* bo = (const float*)d_in[8];
    float* out = (float*)d_out;

    cudaFuncSetAttribute(gemm_mma_kernel,
                         cudaFuncAttributeMaxDynamicSharedMemorySize, GEMM_SMEM);
    cudaFuncSetAttribute(attn_mma_kernel,
                         cudaFuncAttributeMaxDynamicSharedMemorySize, ATTN_SMEM);

    const int n4x = M_ * EMB_ / 4;
    const int n4w = EMB_ * EMB_ / 4;
    conv_split_x<<<n4x / 256, 256>>>(x, n4x);
    conv_split_w<<<dim3(n4w / 256, 4), 256>>>(Wq, Wk, Wv, Wo);

    // QKV projections (mma.sync) -> bf16 hi/lo Q/K/V
    gemm_mma_kernel<<<dim3(EMB_ / 128, M_ / 128, 3), 256, GEMM_SMEM>>>(
        bq, bk, bv, nullptr, 0);

    // causal attention (mma.sync flash, heavy-tiles-first dispatch)
    attn_mma_kernel<<<dim3(B_ * H_, S_ / 128), 256, ATTN_SMEM>>>();

    // output projection (mma.sync)
    gemm_mma_kernel<<<dim3(EMB_ / 128, M_ / 128, 1), 256, GEMM_SMEM>>>(
        bo, nullptr, nullptr, out, 1);
}